// round 1
// baseline (speedup 1.0000x reference)
#include <cuda_runtime.h>
#include <cuda_bf16.h>

// OhemMSELoss: loss = w*(p-t)^2 / 2^25 over N=2^25 elems; mean of top-k (k=262144).
// All losses >= 0 -> IEEE bits are monotone -> 2-level radix select via histograms.

#define N_ELEM   33554432
#define N4       (N_ELEM / 4)
#define K_KEPT   262144u
#define NBIN1    8192      // top 13 bits of float
#define NBIN2    8192      // next 13 bits
#define SHIFT1   19
#define SHIFT2   6

static __device__ float        g_loss[N_ELEM];      // 128 MiB scratch
static __device__ unsigned int g_hist[NBIN1];
static __device__ unsigned int g_sub[NBIN2];
static __device__ double       g_sum_above;
static __device__ int          g_B;
static __device__ unsigned int g_cnt_above;

// ---------------------------------------------------------------- K0: zero state
__global__ void k_zero() {
    int i = blockIdx.x * blockDim.x + threadIdx.x;
    if (i < NBIN1) g_hist[i] = 0u;
    if (i < NBIN2) g_sub[i]  = 0u;
    if (i == 0) { g_sum_above = 0.0; g_B = 0; g_cnt_above = 0u; }
}

// ---------------------------------------------------------------- K1: loss + coarse hist
__global__ __launch_bounds__(256) void k_loss_hist(
    const float4* __restrict__ p,
    const float4* __restrict__ t,
    const float4* __restrict__ w)
{
    __shared__ unsigned int sh[NBIN1];                 // 32 KB
    for (int i = threadIdx.x; i < NBIN1; i += blockDim.x) sh[i] = 0u;
    __syncthreads();

    const float inv = 2.9802322387695312e-08f;        // 1/2^25 (exact)
    float4* out4 = reinterpret_cast<float4*>(g_loss);
    int stride = gridDim.x * blockDim.x;
    for (int i = blockIdx.x * blockDim.x + threadIdx.x; i < N4; i += stride) {
        float4 pv = p[i], tv = t[i], wv = w[i];
        float4 l;
        float dx = pv.x - tv.x; l.x = wv.x * dx * dx * inv;
        float dy = pv.y - tv.y; l.y = wv.y * dy * dy * inv;
        float dz = pv.z - tv.z; l.z = wv.z * dz * dz * inv;
        float dw = pv.w - tv.w; l.w = wv.w * dw * dw * inv;
        out4[i] = l;
        atomicAdd(&sh[__float_as_uint(l.x) >> SHIFT1], 1u);
        atomicAdd(&sh[__float_as_uint(l.y) >> SHIFT1], 1u);
        atomicAdd(&sh[__float_as_uint(l.z) >> SHIFT1], 1u);
        atomicAdd(&sh[__float_as_uint(l.w) >> SHIFT1], 1u);
    }
    __syncthreads();
    for (int i = threadIdx.x; i < NBIN1; i += blockDim.x) {
        unsigned v = sh[i];
        if (v) atomicAdd(&g_hist[i], v);
    }
}

// ---------------------------------------------------------------- K2: find boundary bin
__global__ __launch_bounds__(1024) void k_select1() {
    __shared__ unsigned int s_cnt[NBIN1];              // 32 KB
    __shared__ unsigned int s_chunk[1024];
    int t = threadIdx.x;
    for (int i = t; i < NBIN1; i += 1024) s_cnt[i] = g_hist[i];
    __syncthreads();
    unsigned sum = 0;
    #pragma unroll
    for (int j = 0; j < NBIN1 / 1024; j++) sum += s_cnt[t * (NBIN1 / 1024) + j];
    s_chunk[t] = sum;
    __syncthreads();
    if (t == 0) {
        unsigned cum = 0;
        int B = 0; unsigned above = 0;
        for (int c = 1023; c >= 0; c--) {
            if (cum + s_chunk[c] >= K_KEPT) {
                for (int b = c * 8 + 7; b >= c * 8; b--) {
                    if (cum + s_cnt[b] >= K_KEPT) { B = b; above = cum; goto done; }
                    cum += s_cnt[b];
                }
            } else {
                cum += s_chunk[c];
            }
        }
        done:
        g_B = B;
        g_cnt_above = above;
    }
}

// ---------------------------------------------------------------- K3: exact sum above + sub-hist
__global__ __launch_bounds__(256) void k_refine() {
    __shared__ unsigned int sh[NBIN2];                 // 32 KB
    __shared__ double s_red[8];
    for (int i = threadIdx.x; i < NBIN2; i += blockDim.x) sh[i] = 0u;
    __syncthreads();

    const int B = g_B;
    double local = 0.0;
    const float4* in4 = reinterpret_cast<const float4*>(g_loss);
    int stride = gridDim.x * blockDim.x;
    for (int i = blockIdx.x * blockDim.x + threadIdx.x; i < N4; i += stride) {
        float4 l = in4[i];
        {
            unsigned u = __float_as_uint(l.x); int b = (int)(u >> SHIFT1);
            if (b > B) local += (double)l.x;
            else if (b == B) atomicAdd(&sh[(u >> SHIFT2) & (NBIN2 - 1)], 1u);
        }
        {
            unsigned u = __float_as_uint(l.y); int b = (int)(u >> SHIFT1);
            if (b > B) local += (double)l.y;
            else if (b == B) atomicAdd(&sh[(u >> SHIFT2) & (NBIN2 - 1)], 1u);
        }
        {
            unsigned u = __float_as_uint(l.z); int b = (int)(u >> SHIFT1);
            if (b > B) local += (double)l.z;
            else if (b == B) atomicAdd(&sh[(u >> SHIFT2) & (NBIN2 - 1)], 1u);
        }
        {
            unsigned u = __float_as_uint(l.w); int b = (int)(u >> SHIFT1);
            if (b > B) local += (double)l.w;
            else if (b == B) atomicAdd(&sh[(u >> SHIFT2) & (NBIN2 - 1)], 1u);
        }
    }
    // block-reduce the double sum
    #pragma unroll
    for (int o = 16; o; o >>= 1) local += __shfl_down_sync(0xffffffffu, local, o);
    if ((threadIdx.x & 31) == 0) s_red[threadIdx.x >> 5] = local;
    __syncthreads();
    if (threadIdx.x < 8) {
        double v = s_red[threadIdx.x];
        #pragma unroll
        for (int o = 4; o; o >>= 1) v += __shfl_down_sync(0xffu, v, o);
        if (threadIdx.x == 0) atomicAdd(&g_sum_above, v);
    }
    __syncthreads();
    for (int i = threadIdx.x; i < NBIN2; i += blockDim.x) {
        unsigned v = sh[i];
        if (v) atomicAdd(&g_sub[i], v);
    }
}

// ---------------------------------------------------------------- K4: finalize
__global__ __launch_bounds__(1024) void k_final(float* __restrict__ out) {
    __shared__ unsigned int s_cnt[NBIN2];              // 32 KB
    __shared__ unsigned int s_c[1024];
    __shared__ double       s_w[1024];
    int t = threadIdx.x;
    const unsigned B = (unsigned)g_B;
    for (int i = t; i < NBIN2; i += 1024) s_cnt[i] = g_sub[i];
    __syncthreads();
    unsigned csum = 0; double wsum = 0.0;
    #pragma unroll
    for (int j = 0; j < NBIN2 / 1024; j++) {
        int b = t * (NBIN2 / 1024) + j;
        unsigned c = s_cnt[b];
        csum += c;
        if (c) {
            unsigned rep = (B << SHIFT1) | ((unsigned)b << SHIFT2) | (1u << (SHIFT2 - 1));
            wsum += (double)c * (double)__uint_as_float(rep);
        }
    }
    s_c[t] = csum; s_w[t] = wsum;
    __syncthreads();
    if (t == 0) {
        unsigned r = K_KEPT - g_cnt_above;             // 1 <= r <= cnt(B)
        double sum = g_sum_above;
        unsigned cum = 0;
        for (int c = 1023; c >= 0; c--) {
            if (cum + s_c[c] >= r) {
                for (int b = c * 8 + 7; b >= c * 8; b--) {
                    unsigned cnt = s_cnt[b];
                    unsigned rep = (B << SHIFT1) | ((unsigned)b << SHIFT2) | (1u << (SHIFT2 - 1));
                    double v = (double)__uint_as_float(rep);
                    if (cum + cnt >= r) { sum += (double)(r - cum) * v; goto done; }
                    cum += cnt; sum += (double)cnt * v;
                }
            } else {
                cum += s_c[c]; sum += s_w[c];
            }
        }
        done:
        out[0] = (float)(sum / (double)K_KEPT);
    }
}

// ---------------------------------------------------------------- launch
extern "C" void kernel_launch(void* const* d_in, const int* in_sizes, int n_in,
                              void* d_out, int out_size) {
    const float4* p = (const float4*)d_in[0];   // predict
    const float4* t = (const float4*)d_in[1];   // target
    const float4* w = (const float4*)d_in[2];   // weight
    float* out = (float*)d_out;

    k_zero<<<32, 256>>>();
    k_loss_hist<<<1036, 256>>>(p, t, w);        // 7 blocks/SM (32KB smem each)
    k_select1<<<1, 1024>>>();
    k_refine<<<1036, 256>>>();
    k_final<<<1, 1024>>>(out);
}

// round 2
// speedup vs baseline: 2.2544x; 2.2544x over previous
#include <cuda_runtime.h>
#include <cuda_bf16.h>
#include <cuda_fp16.h>

// OhemMSELoss: loss = w*(p-t)^2 / 2^25 over N=2^25 elems; mean of top-k (k=262144).
// Store UNNORMALIZED loss (w*d^2) as fp16 (64 MiB scratch -> fits L2).
// All values >= 0 -> half bits monotone -> radix select: 13-bit coarse hist,
// then exact 8-value sub-histogram of the 3 remaining bits. Divide by 2^25*K at end.

#define N_ELEM   33554432
#define N4       (N_ELEM / 4)          // float4 count per stream = 2^23
#define NU4      (N_ELEM / 8)          // uint4 count of half scratch = 2^22
#define K_KEPT   262144u
#define NBIN1    8192                  // half bits >> 3

static __device__ __half       g_lossh[N_ELEM];     // 64 MiB scratch (fits L2)
static __device__ unsigned int g_hist[NBIN1];
static __device__ unsigned int g_sub[8];
static __device__ double       g_sum_above;
static __device__ int          g_B;
static __device__ unsigned int g_cnt_above;

// ---------------------------------------------------------------- K0: zero state
__global__ void k_zero() {
    int i = blockIdx.x * blockDim.x + threadIdx.x;
    if (i < NBIN1) g_hist[i] = 0u;
    if (i < 8)     g_sub[i]  = 0u;
    if (i == 0) { g_sum_above = 0.0; g_B = 0; g_cnt_above = 0u; }
}

// ---------------------------------------------------------------- K1: loss + coarse hist
__global__ __launch_bounds__(256) void k_loss_hist(
    const float4* __restrict__ p,
    const float4* __restrict__ t,
    const float4* __restrict__ w)
{
    __shared__ unsigned int sh[NBIN1];                 // 32 KB
    for (int i = threadIdx.x; i < NBIN1; i += blockDim.x) sh[i] = 0u;
    __syncthreads();

    uint2* out2 = reinterpret_cast<uint2*>(g_lossh);   // 4 halves per float4
    const int T = gridDim.x * blockDim.x;

    for (int i0 = blockIdx.x * blockDim.x + threadIdx.x; i0 < N4; i0 += 2 * T) {
        const int i1 = i0 + T;
        const bool has1 = (i1 < N4);

        // batch all loads up front -> high MLP (6 independent LDG.128)
        float4 p0 = __ldcs(&p[i0]);
        float4 t0 = __ldcs(&t[i0]);
        float4 w0 = __ldcs(&w[i0]);
        float4 p1, t1, w1;
        if (has1) { p1 = __ldcs(&p[i1]); t1 = __ldcs(&t[i1]); w1 = __ldcs(&w[i1]); }

        {
            float dx = p0.x - t0.x, dy = p0.y - t0.y, dz = p0.z - t0.z, dw = p0.w - t0.w;
            float lx = w0.x * dx * dx, ly = w0.y * dy * dy;
            float lz = w0.z * dz * dz, lw = w0.w * dw * dw;
            __half2 ha = __floats2half2_rn(lx, ly);
            __half2 hb = __floats2half2_rn(lz, lw);
            unsigned ua = *reinterpret_cast<unsigned*>(&ha);
            unsigned ub = *reinterpret_cast<unsigned*>(&hb);
            out2[i0] = make_uint2(ua, ub);
            atomicAdd(&sh[(ua & 0xFFFFu) >> 3], 1u);
            atomicAdd(&sh[(ua >> 19)],          1u);   // (ua>>16)>>3
            atomicAdd(&sh[(ub & 0xFFFFu) >> 3], 1u);
            atomicAdd(&sh[(ub >> 19)],          1u);
        }
        if (has1) {
            float dx = p1.x - t1.x, dy = p1.y - t1.y, dz = p1.z - t1.z, dw = p1.w - t1.w;
            float lx = w1.x * dx * dx, ly = w1.y * dy * dy;
            float lz = w1.z * dz * dz, lw = w1.w * dw * dw;
            __half2 ha = __floats2half2_rn(lx, ly);
            __half2 hb = __floats2half2_rn(lz, lw);
            unsigned ua = *reinterpret_cast<unsigned*>(&ha);
            unsigned ub = *reinterpret_cast<unsigned*>(&hb);
            out2[i1] = make_uint2(ua, ub);
            atomicAdd(&sh[(ua & 0xFFFFu) >> 3], 1u);
            atomicAdd(&sh[(ua >> 19)],          1u);
            atomicAdd(&sh[(ub & 0xFFFFu) >> 3], 1u);
            atomicAdd(&sh[(ub >> 19)],          1u);
        }
    }
    __syncthreads();
    for (int i = threadIdx.x; i < NBIN1; i += blockDim.x) {
        unsigned v = sh[i];
        if (v) atomicAdd(&g_hist[i], v);
    }
}

// ---------------------------------------------------------------- K2: find boundary bin
__global__ __launch_bounds__(1024) void k_select1() {
    __shared__ unsigned int s_cnt[NBIN1];              // 32 KB
    __shared__ unsigned int s_chunk[1024];
    int t = threadIdx.x;
    for (int i = t; i < NBIN1; i += 1024) s_cnt[i] = g_hist[i];
    __syncthreads();
    unsigned sum = 0;
    #pragma unroll
    for (int j = 0; j < NBIN1 / 1024; j++) sum += s_cnt[t * (NBIN1 / 1024) + j];
    s_chunk[t] = sum;
    __syncthreads();
    if (t == 0) {
        unsigned cum = 0;
        int B = 0; unsigned above = 0;
        for (int c = 1023; c >= 0; c--) {
            if (cum + s_chunk[c] >= K_KEPT) {
                for (int b = c * 8 + 7; b >= c * 8; b--) {
                    if (cum + s_cnt[b] >= K_KEPT) { B = b; above = cum; goto done; }
                    cum += s_cnt[b];
                }
            } else {
                cum += s_chunk[c];
            }
        }
        done:
        g_B = B;
        g_cnt_above = above;
    }
}

// ---------------------------------------------------------------- K3: sum above + 3-bit sub-hist
__global__ __launch_bounds__(256) void k_refine() {
    __shared__ unsigned int shsub[8];
    __shared__ double s_red[8];
    if (threadIdx.x < 8) shsub[threadIdx.x] = 0u;
    __syncthreads();

    const int B = g_B;
    float fsum = 0.0f;                     // <=~ a few elems per thread above thr
    const uint4* in4 = reinterpret_cast<const uint4*>(g_lossh);
    const int T = gridDim.x * blockDim.x;

    for (int i0 = blockIdx.x * blockDim.x + threadIdx.x; i0 < NU4; i0 += 4 * T) {
        uint4 v0, v1, v2, v3;
        const int i1 = i0 + T, i2 = i0 + 2 * T, i3 = i0 + 3 * T;
        v0 = in4[i0];                               // 4 independent LDG.128
        const bool h1 = i1 < NU4, h2 = i2 < NU4, h3 = i3 < NU4;
        if (h1) v1 = in4[i1];
        if (h2) v2 = in4[i2];
        if (h3) v3 = in4[i3];

        #define PROC_WORD(uw) do {                                                 \
            unsigned _u = (uw);                                                    \
            unsigned short _s0 = (unsigned short)(_u & 0xFFFFu);                   \
            unsigned short _s1 = (unsigned short)(_u >> 16);                       \
            int _b0 = _s0 >> 3, _b1 = _s1 >> 3;                                    \
            if (_b0 > B) fsum += __half2float(__ushort_as_half(_s0));              \
            else if (_b0 == B) atomicAdd(&shsub[_s0 & 7u], 1u);                    \
            if (_b1 > B) fsum += __half2float(__ushort_as_half(_s1));              \
            else if (_b1 == B) atomicAdd(&shsub[_s1 & 7u], 1u);                    \
        } while (0)

        PROC_WORD(v0.x); PROC_WORD(v0.y); PROC_WORD(v0.z); PROC_WORD(v0.w);
        if (h1) { PROC_WORD(v1.x); PROC_WORD(v1.y); PROC_WORD(v1.z); PROC_WORD(v1.w); }
        if (h2) { PROC_WORD(v2.x); PROC_WORD(v2.y); PROC_WORD(v2.z); PROC_WORD(v2.w); }
        if (h3) { PROC_WORD(v3.x); PROC_WORD(v3.y); PROC_WORD(v3.z); PROC_WORD(v3.w); }
        #undef PROC_WORD
    }

    // block-reduce the sum (double from here on)
    double local = (double)fsum;
    #pragma unroll
    for (int o = 16; o; o >>= 1) local += __shfl_down_sync(0xffffffffu, local, o);
    if ((threadIdx.x & 31) == 0) s_red[threadIdx.x >> 5] = local;
    __syncthreads();
    if (threadIdx.x < 8) {
        double v = s_red[threadIdx.x];
        #pragma unroll
        for (int o = 4; o; o >>= 1) v += __shfl_down_sync(0xffu, v, o);
        if (threadIdx.x == 0) atomicAdd(&g_sum_above, v);
    }
    __syncthreads();
    if (threadIdx.x < 8) {
        unsigned v = shsub[threadIdx.x];
        if (v) atomicAdd(&g_sub[threadIdx.x], v);
    }
}

// ---------------------------------------------------------------- K4: finalize
__global__ void k_final(float* __restrict__ out) {
    if (threadIdx.x == 0 && blockIdx.x == 0) {
        unsigned r = K_KEPT - g_cnt_above;             // 1 <= r <= cnt(bin B)
        double sum = g_sum_above;
        unsigned B = (unsigned)g_B;
        for (int j = 7; j >= 0; j--) {
            unsigned c = g_sub[j];
            unsigned short pat = (unsigned short)((B << 3) | (unsigned)j);
            double v = (double)__half2float(__ushort_as_half(pat));   // exact
            if (c >= r) { sum += (double)r * v; break; }
            sum += (double)c * v; r -= c;
        }
        // divide by (2^25 * K) = 2^43
        out[0] = (float)(sum / 8796093022208.0);
    }
}

// ---------------------------------------------------------------- launch
extern "C" void kernel_launch(void* const* d_in, const int* in_sizes, int n_in,
                              void* d_out, int out_size) {
    const float4* p = (const float4*)d_in[0];   // predict
    const float4* t = (const float4*)d_in[1];   // target
    const float4* w = (const float4*)d_in[2];   // weight
    float* out = (float*)d_out;

    k_zero<<<32, 256>>>();
    k_loss_hist<<<888, 256>>>(p, t, w);         // 6 blocks/SM (32KB smem), MLP=6
    k_select1<<<1, 1024>>>();
    k_refine<<<1184, 256>>>();                  // MLP=4, scratch mostly L2-resident
    k_final<<<1, 32>>>(out);
}